// round 15
// baseline (speedup 1.0000x reference)
#include <cuda_runtime.h>
#include <cuda_fp16.h>
#include <stdint.h>
#include <math.h>

#define NPTS 262144
#define NP 10
#define NL 16
#define TSZ (1u << 19)

#define SCALE 8192.0f
#define INV_SCALE (1.0f / 8192.0f)

// emb: per point 16 level-slots of 48B (12 half2: 10 used), 768B/pt
__device__ __half g_emb[(size_t)NPTS * 384];
__device__ uint4  g_tabT[(size_t)NL * TSZ * 4];

struct ResParams { float gs[NL]; };

__device__ __forceinline__ float tanh_fast(float x) {
    float r; asm("tanh.approx.f32 %0, %1;" : "=f"(r) : "f"(x)); return r;
}
__device__ __forceinline__ float sigm_t(float x) {
    return fmaf(0.5f, tanh_fast(0.5f * x), 0.5f);
}

// ===================== Kernel T: table transpose =====================
__global__ __launch_bounds__(256)
void transpose_kernel(const float2* __restrict__ tab)
{
    size_t idx = (size_t)blockIdx.x * 256 + threadIdx.x;
    unsigned u[NP];
    #pragma unroll
    for (int p = 0; p < NP; ++p) {
        float2 v = __ldg(tab + (size_t)p * ((size_t)NL * TSZ) + idx);
        __half2 h = __floats2half2_rn(v.x * SCALE, v.y * SCALE);
        u[p] = *reinterpret_cast<unsigned*>(&h);
    }
    uint4* dst = g_tabT + idx * 4;
    dst[0] = make_uint4(u[0], u[1], u[2], u[3]);
    dst[1] = make_uint4(u[4], u[5], u[6], u[7]);
    dst[2] = make_uint4(u[8], u[9], u[8], u[9]);
}

// ===================== Kernel A: hash-grid gather =====================
__global__ __launch_bounds__(256, 2)
void gather_kernel(const float* __restrict__ xyzt, ResParams rp)
{
    const int l    = blockIdx.y;
    const int ptid = blockIdx.x * 256 + threadIdx.x;

    const float gsv = rp.gs[l];
    float4 ptq = reinterpret_cast<const float4*>(xyzt)[ptid];
    float x = fminf(fmaxf(ptq.x, -1.0f), 1.0f);
    float y = fminf(fmaxf(ptq.y, -1.0f), 1.0f);
    float z = fminf(fmaxf(ptq.z, -1.0f), 1.0f);
    float bx = floorf(__fdiv_rn(x + 1.0f, gsv));
    float by = floorf(__fdiv_rn(y + 1.0f, gsv));
    float bz = floorf(__fdiv_rn(z + 1.0f, gsv));
    float wx = __fdiv_rn(x - (bx * gsv - 1.0f), gsv);
    float wy = __fdiv_rn(y - (by * gsv - 1.0f), gsv);
    float wz = __fdiv_rn(z - (bz * gsv - 1.0f), gsv);

    unsigned ix = (unsigned)(int)bx;
    unsigned iy = (unsigned)(int)by;
    unsigned iz = (unsigned)(int)bz;
    unsigned hy0 = iy * 2654435761u, hy1 = hy0 + 2654435761u;
    unsigned hz0 = iz * 805459861u,  hz1 = hz0 + 805459861u;

    unsigned hidx[8];
    float    wc[8];
    float wx1 = 1.0f - wx, wy1 = 1.0f - wy, wz1 = 1.0f - wz;
    #pragma unroll
    for (int c = 0; c < 8; ++c) {
        unsigned hx = ix + ((c >> 2) & 1);
        unsigned hy = (c & 2) ? hy1 : hy0;
        unsigned hz = (c & 1) ? hz1 : hz0;
        hidx[c] = (hx ^ hy ^ hz) & (TSZ - 1u);
        wc[c] = (((c >> 2) & 1) ? wx : wx1) * ((c & 2) ? wy : wy1) * ((c & 1) ? wz : wz1);
    }

    const uint4* lvl = g_tabT + (size_t)l * TSZ * 4;
    float sx[NP], sy[NP];
    #pragma unroll
    for (int p = 0; p < NP; ++p) { sx[p] = 0.0f; sy[p] = 0.0f; }

    {
        uint4 va[8], vb[8];
        uint2 vcc[8];
        #pragma unroll
        for (int c = 0; c < 8; ++c) {
            const uint4* s = lvl + (size_t)hidx[c] * 4;
            va[c]  = __ldg(s);
            vb[c]  = __ldg(s + 1);
            vcc[c] = __ldg(reinterpret_cast<const uint2*>(s + 2));
        }
        #pragma unroll
        for (int c = 0; c < 8; ++c) {
            float w = wc[c];
            unsigned u[NP] = {va[c].x, va[c].y, va[c].z, va[c].w,
                              vb[c].x, vb[c].y, vb[c].z, vb[c].w,
                              vcc[c].x, vcc[c].y};
            #pragma unroll
            for (int p = 0; p < NP; ++p) {
                float2 f = __half22float2(*reinterpret_cast<__half2*>(&u[p]));
                sx[p] = fmaf(w, f.x, sx[p]);
                sy[p] = fmaf(w, f.y, sy[p]);
            }
        }
    }

    unsigned up[NP];
    #pragma unroll
    for (int p = 0; p < NP; ++p) {
        __half2 h = __floats2half2_rn(sx[p], sy[p]);   // pre-scaled by 8192
        up[p] = *reinterpret_cast<unsigned*>(&h);
    }
    char* dst = reinterpret_cast<char*>(g_emb) + (size_t)ptid * 768 + l * 48;
    *reinterpret_cast<uint4*>(dst)      = make_uint4(up[0], up[1], up[2], up[3]);
    *reinterpret_cast<uint4*>(dst + 16) = make_uint4(up[4], up[5], up[6], up[7]);
    *reinterpret_cast<uint2*>(dst + 32) = make_uint2(up[8], up[9]);
}

// ===================== Kernel B: HMMA GRU + output (fp16 accumulate) =====================
#define GB_WIH  0
#define GB_WHH  30720
#define GB_WFC  61440
#define GB_ANC  61696
#define GB_SMEM 64256

#define W_STR 80

// fp16-accumulate HMMA: D/C are 2 b32 regs (rows g -> .x halves, rows g+8 -> .y halves)
__device__ __forceinline__ void mma16816h(uint2& d, const unsigned* a,
                                          unsigned b0, unsigned b1) {
    asm volatile(
        "mma.sync.aligned.m16n8k16.row.col.f16.f16.f16.f16 "
        "{%0,%1}, {%2,%3,%4,%5}, {%6,%7}, {%0,%1};"
        : "+r"(d.x), "+r"(d.y)
        : "r"(a[0]), "r"(a[1]), "r"(a[2]), "r"(a[3]), "r"(b0), "r"(b1));
}
__device__ __forceinline__ unsigned pack_h2(float lo, float hi) {
    __half2 h = __floats2half2_rn(lo, hi);
    return *reinterpret_cast<unsigned*>(&h);
}
__device__ __forceinline__ int wperm(int n, int k) {
    int kt = k >> 4, r = k & 15;
    int slot = ((r & 7) >> 1) * 4 + (r >> 3) * 2 + (r & 1);
    return n * W_STR + kt * 16 + slot;
}

__global__ __launch_bounds__(128)
void gru_mma_kernel(const float* __restrict__ xyzt,
                    const float* __restrict__ w_ih,
                    const float* __restrict__ w_hh,
                    const float* __restrict__ w_fc,
                    float* __restrict__ out)
{
    extern __shared__ char smc[];
    __half* wih  = reinterpret_cast<__half*>(smc + GB_WIH);
    __half* whh  = reinterpret_cast<__half*>(smc + GB_WHH);
    float*  wfcs = reinterpret_cast<float*>(smc + GB_WFC);
    float*  ancs = reinterpret_cast<float*>(smc + GB_ANC);

    const int tid = threadIdx.x;

    for (int i = tid; i < 192 * 32; i += 128) {
        int n = i >> 5, k = i & 31;
        wih[wperm(n, k)] = __float2half_rn(w_ih[i]);
    }
    for (int i = tid; i < 192 * 64; i += 128) {
        int n = i >> 6, k = i & 63;
        whh[wperm(n, k)] = __float2half_rn(w_hh[i]);
    }
    if (tid < 64) wfcs[tid] = w_fc[tid];
    __syncthreads();

    const int lane  = tid & 31;
    const int wrp   = tid >> 5;
    const int g     = lane >> 2;
    const int t4    = lane & 3;
    const int pbase = wrp * 16;
    const int gpt0  = blockIdx.x * 64 + pbase;
    const int ptA   = gpt0 + g;
    const int ptB   = gpt0 + g + 8;

    float wfr[16];
    #pragma unroll
    for (int jt = 0; jt < 8; ++jt) {
        wfr[2 * jt]     = wfcs[jt * 8 + t4 * 2];
        wfr[2 * jt + 1] = wfcs[jt * 8 + t4 * 2 + 1];
    }

    float hD[8][4];
    #pragma unroll
    for (int i = 0; i < 8; ++i)
        { hD[i][0]=0.f; hD[i][1]=0.f; hD[i][2]=0.f; hD[i][3]=0.f; }
    float anc0 = 0.0f, anc1 = 0.0f;

    const __half* eA = g_emb + (size_t)ptA * 384;
    const __half* eB = g_emb + (size_t)ptB * 384;

    for (int p = 0; p < NP; ++p) {
        // emb A fragments, KEPT SCALED (x8192): healthy fp16 range for f16 accum
        unsigned ea[2][4];
        #pragma unroll
        for (int kt = 0; kt < 2; ++kt) {
            int l0 = kt * 8 + t4;
            ea[kt][0] = *reinterpret_cast<const unsigned*>(eA + (l0 * 12 + p) * 2);
            ea[kt][1] = *reinterpret_cast<const unsigned*>(eB + (l0 * 12 + p) * 2);
            ea[kt][2] = *reinterpret_cast<const unsigned*>(eA + ((l0 + 4) * 12 + p) * 2);
            ea[kt][3] = *reinterpret_cast<const unsigned*>(eB + ((l0 + 4) * 12 + p) * 2);
        }
        unsigned ha[4][4];
        if (p > 0) {
            #pragma unroll
            for (int kt = 0; kt < 4; ++kt) {
                ha[kt][0] = pack_h2(hD[2*kt][0],   hD[2*kt][1]);
                ha[kt][1] = pack_h2(hD[2*kt][2],   hD[2*kt][3]);
                ha[kt][2] = pack_h2(hD[2*kt+1][0], hD[2*kt+1][1]);
                ha[kt][3] = pack_h2(hD[2*kt+1][2], hD[2*kt+1][3]);
            }
        }

        float fcp0 = 0.0f, fcp1 = 0.0f;

        #pragma unroll
        for (int jt = 0; jt < 8; ++jt) {
            uint2 gR = make_uint2(0, 0), gZ = make_uint2(0, 0), gN = make_uint2(0, 0);
            uint2 hR = make_uint2(0, 0), hZ = make_uint2(0, 0), hH = make_uint2(0, 0);
            const int nR = (jt * 8 + g) * W_STR;
            const int nZ = (64 + jt * 8 + g) * W_STR;
            const int nN = (128 + jt * 8 + g) * W_STR;

            #pragma unroll
            for (int kt = 0; kt < 2; ++kt) {
                int ko = kt * 16 + t4 * 4;
                uint2 bR = *reinterpret_cast<const uint2*>(wih + nR + ko);
                uint2 bZ = *reinterpret_cast<const uint2*>(wih + nZ + ko);
                uint2 bN = *reinterpret_cast<const uint2*>(wih + nN + ko);
                mma16816h(gR, ea[kt], bR.x, bR.y);
                mma16816h(gZ, ea[kt], bZ.x, bZ.y);
                mma16816h(gN, ea[kt], bN.x, bN.y);
            }
            if (p > 0) {
                #pragma unroll
                for (int kt = 0; kt < 4; ++kt) {
                    int ko = kt * 16 + t4 * 4;
                    uint2 bR = *reinterpret_cast<const uint2*>(whh + nR + ko);
                    uint2 bZ = *reinterpret_cast<const uint2*>(whh + nZ + ko);
                    uint2 bH = *reinterpret_cast<const uint2*>(whh + nN + ko);
                    mma16816h(hR, ha[kt], bR.x, bR.y);
                    mma16816h(hZ, ha[kt], bZ.x, bZ.y);
                    mma16816h(hH, ha[kt], bH.x, bH.y);
                }
            }
            // unpack: .x = rows g (i=0,1), .y = rows g+8 (i=2,3)
            float2 giR0 = __half22float2(*reinterpret_cast<__half2*>(&gR.x));
            float2 giR1 = __half22float2(*reinterpret_cast<__half2*>(&gR.y));
            float2 giZ0 = __half22float2(*reinterpret_cast<__half2*>(&gZ.x));
            float2 giZ1 = __half22float2(*reinterpret_cast<__half2*>(&gZ.y));
            float2 giN0 = __half22float2(*reinterpret_cast<__half2*>(&gN.x));
            float2 giN1 = __half22float2(*reinterpret_cast<__half2*>(&gN.y));
            float2 ghR0 = __half22float2(*reinterpret_cast<__half2*>(&hR.x));
            float2 ghR1 = __half22float2(*reinterpret_cast<__half2*>(&hR.y));
            float2 ghZ0 = __half22float2(*reinterpret_cast<__half2*>(&hZ.x));
            float2 ghZ1 = __half22float2(*reinterpret_cast<__half2*>(&hZ.y));
            float2 ghH0 = __half22float2(*reinterpret_cast<__half2*>(&hH.x));
            float2 ghH1 = __half22float2(*reinterpret_cast<__half2*>(&hH.y));

            float giRv[4] = {giR0.x, giR0.y, giR1.x, giR1.y};
            float giZv[4] = {giZ0.x, giZ0.y, giZ1.x, giZ1.y};
            float giNv[4] = {giN0.x, giN0.y, giN1.x, giN1.y};
            float ghRv[4] = {ghR0.x, ghR0.y, ghR1.x, ghR1.y};
            float ghZv[4] = {ghZ0.x, ghZ0.y, ghZ1.x, ghZ1.y};
            float ghHv[4] = {ghH0.x, ghH0.y, ghH1.x, ghH1.y};

            #pragma unroll
            for (int i = 0; i < 4; ++i) {
                float r = sigm_t(fmaf(giRv[i], INV_SCALE, ghRv[i]));
                float z = sigm_t(fmaf(giZv[i], INV_SCALE, ghZv[i]));
                float n = tanh_fast(fmaf(r, ghHv[i], giNv[i] * INV_SCALE));
                float h = fmaf(z, hD[jt][i] - n, n);
                hD[jt][i] = h;
                float wv = wfr[2 * jt + (i & 1)];
                if (i < 2) fcp0 = fmaf(h, wv, fcp0);
                else       fcp1 = fmaf(h, wv, fcp1);
            }
        }
        fcp0 += __shfl_xor_sync(0xffffffffu, fcp0, 1);
        fcp0 += __shfl_xor_sync(0xffffffffu, fcp0, 2);
        fcp1 += __shfl_xor_sync(0xffffffffu, fcp1, 1);
        fcp1 += __shfl_xor_sync(0xffffffffu, fcp1, 2);
        anc0 += __fdiv_rn(fcp0 * 2.0f, 10.0f);
        anc1 += __fdiv_rn(fcp1 * 2.0f, 10.0f);
        if (t4 == 0) {
            ancs[(pbase + g) * NP + p]     = anc0;
            ancs[(pbase + g + 8) * NP + p] = anc1;
        }
    }
    __syncwarp();

    for (int q = 0; q < 16; ++q) {
        int pt = gpt0 + q;
        float t = xyzt[(size_t)pt * 4 + 3];
        float lg[NP];
        float mx = -1e30f;
        #pragma unroll
        for (int p = 0; p < NP; ++p) {
            float a = ancs[(pbase + q) * NP + p];
            float L = -__fdiv_rn(fabsf(t - a), 100.0f);
            lg[p] = L;
            mx = fmaxf(mx, L);
        }
        float s = 0.0f, o = 0.0f;
        #pragma unroll
        for (int p = 0; p < NP; ++p) {
            float w = __expf(lg[p] - mx);
            s += w;
            o += w * __half2float(g_emb[(size_t)pt * 384 + ((lane >> 1) * 12 + p) * 2 + (lane & 1)]);
        }
        out[(size_t)pt * 32 + lane] = __fdiv_rn(o, s) * INV_SCALE;
    }
}

extern "C" void kernel_launch(void* const* d_in, const int* in_sizes, int n_in,
                              void* d_out, int out_size)
{
    const float*  xyzt = (const float*)d_in[0];
    const float2* tab  = (const float2*)d_in[1];
    const float*  w_ih = (const float*)d_in[2];
    const float*  w_hh = (const float*)d_in[3];
    const float*  w_fc = (const float*)d_in[4];
    float* out = (float*)d_out;

    ResParams rp;
    double B = exp((log(4096.0) - log(128.0)) / 15.0);
    for (int l = 0; l < NL; ++l) {
        double v = floor(128.0 * pow(B, (double)l));
        rp.gs[l] = 2.0f / (float)v;
    }

    dim3 gridT((unsigned)(((size_t)NL * TSZ) / 256));
    transpose_kernel<<<gridT, 256>>>(tab);

    dim3 gridA(NPTS / 256, NL);
    gather_kernel<<<gridA, 256>>>(xyzt, rp);

    cudaFuncSetAttribute(gru_mma_kernel, cudaFuncAttributeMaxDynamicSharedMemorySize, GB_SMEM);
    gru_mma_kernel<<<NPTS / 64, 128, GB_SMEM>>>(xyzt, w_ih, w_hh, w_fc, out);
}

// round 16
// speedup vs baseline: 1.4759x; 1.4759x over previous
#include <cuda_runtime.h>
#include <cuda_fp16.h>
#include <stdint.h>
#include <math.h>

#define NPTS 262144
#define NP 10
#define NL 16
#define TSZ (1u << 19)

#define SCALE 8192.0f
#define INV_SCALE (1.0f / 8192.0f)

// emb: per point 16 level-slots of 48B (12 half2: 10 used), 768B/pt
__device__ __half g_emb[(size_t)NPTS * 384];
__device__ uint4  g_tabT[(size_t)NL * TSZ * 4];

struct ResParams { float gs[NL]; };

__device__ __forceinline__ float tanh_fast(float x) {
    float r; asm("tanh.approx.f32 %0, %1;" : "=f"(r) : "f"(x)); return r;
}
__device__ __forceinline__ float sigm_t(float x) {
    return fmaf(0.5f, tanh_fast(0.5f * x), 0.5f);
}

// ===================== Kernel T: table transpose (smem-staged coalesced writes) =====
__global__ __launch_bounds__(256)
void transpose_kernel(const float2* __restrict__ tab)
{
    __shared__ uint4 stg[256 * 5];           // 80B stride per entry: conflict-free
    const int t = threadIdx.x;
    size_t idx = (size_t)blockIdx.x * 256 + t;

    unsigned u[NP];
    #pragma unroll
    for (int p = 0; p < NP; ++p) {
        float2 v = __ldg(tab + (size_t)p * ((size_t)NL * TSZ) + idx);
        __half2 h = __floats2half2_rn(v.x * SCALE, v.y * SCALE);
        u[p] = *reinterpret_cast<unsigned*>(&h);
    }
    stg[t * 5 + 0] = make_uint4(u[0], u[1], u[2], u[3]);
    stg[t * 5 + 1] = make_uint4(u[4], u[5], u[6], u[7]);
    stg[t * 5 + 2] = make_uint4(u[8], u[9], u[8], u[9]);
    stg[t * 5 + 3] = make_uint4(0, 0, 0, 0);   // pad slot to full 64B
    __syncthreads();

    // coalesced copy-out: 1024 contiguous uint4 for this block's 256 entries
    uint4* dst = g_tabT + ((size_t)blockIdx.x * 256) * 4;
    #pragma unroll
    for (int k = 0; k < 4; ++k) {
        int i = t + k * 256;                  // linear uint4 index in block region
        dst[i] = stg[(i >> 2) * 5 + (i & 3)];
    }
}

// ===================== Kernel A: hash-grid gather (unchanged from R14) =====================
__global__ __launch_bounds__(256, 2)
void gather_kernel(const float* __restrict__ xyzt, ResParams rp)
{
    const int l    = blockIdx.y;
    const int ptid = blockIdx.x * 256 + threadIdx.x;

    const float gsv = rp.gs[l];
    float4 ptq = reinterpret_cast<const float4*>(xyzt)[ptid];
    float x = fminf(fmaxf(ptq.x, -1.0f), 1.0f);
    float y = fminf(fmaxf(ptq.y, -1.0f), 1.0f);
    float z = fminf(fmaxf(ptq.z, -1.0f), 1.0f);
    float bx = floorf(__fdiv_rn(x + 1.0f, gsv));
    float by = floorf(__fdiv_rn(y + 1.0f, gsv));
    float bz = floorf(__fdiv_rn(z + 1.0f, gsv));
    float wx = __fdiv_rn(x - (bx * gsv - 1.0f), gsv);
    float wy = __fdiv_rn(y - (by * gsv - 1.0f), gsv);
    float wz = __fdiv_rn(z - (bz * gsv - 1.0f), gsv);

    unsigned ix = (unsigned)(int)bx;
    unsigned iy = (unsigned)(int)by;
    unsigned iz = (unsigned)(int)bz;
    unsigned hy0 = iy * 2654435761u, hy1 = hy0 + 2654435761u;
    unsigned hz0 = iz * 805459861u,  hz1 = hz0 + 805459861u;

    unsigned hidx[8];
    float    wc[8];
    float wx1 = 1.0f - wx, wy1 = 1.0f - wy, wz1 = 1.0f - wz;
    #pragma unroll
    for (int c = 0; c < 8; ++c) {
        unsigned hx = ix + ((c >> 2) & 1);
        unsigned hy = (c & 2) ? hy1 : hy0;
        unsigned hz = (c & 1) ? hz1 : hz0;
        hidx[c] = (hx ^ hy ^ hz) & (TSZ - 1u);
        wc[c] = (((c >> 2) & 1) ? wx : wx1) * ((c & 2) ? wy : wy1) * ((c & 1) ? wz : wz1);
    }

    const uint4* lvl = g_tabT + (size_t)l * TSZ * 4;
    float sx[NP], sy[NP];
    #pragma unroll
    for (int p = 0; p < NP; ++p) { sx[p] = 0.0f; sy[p] = 0.0f; }

    {
        uint4 va[8], vb[8];
        uint2 vcc[8];
        #pragma unroll
        for (int c = 0; c < 8; ++c) {
            const uint4* s = lvl + (size_t)hidx[c] * 4;
            va[c]  = __ldg(s);
            vb[c]  = __ldg(s + 1);
            vcc[c] = __ldg(reinterpret_cast<const uint2*>(s + 2));
        }
        #pragma unroll
        for (int c = 0; c < 8; ++c) {
            float w = wc[c];
            unsigned u[NP] = {va[c].x, va[c].y, va[c].z, va[c].w,
                              vb[c].x, vb[c].y, vb[c].z, vb[c].w,
                              vcc[c].x, vcc[c].y};
            #pragma unroll
            for (int p = 0; p < NP; ++p) {
                float2 f = __half22float2(*reinterpret_cast<__half2*>(&u[p]));
                sx[p] = fmaf(w, f.x, sx[p]);
                sy[p] = fmaf(w, f.y, sy[p]);
            }
        }
    }

    unsigned up[NP];
    #pragma unroll
    for (int p = 0; p < NP; ++p) {
        __half2 h = __floats2half2_rn(sx[p], sy[p]);   // pre-scaled by 8192
        up[p] = *reinterpret_cast<unsigned*>(&h);
    }
    char* dst = reinterpret_cast<char*>(g_emb) + (size_t)ptid * 768 + l * 48;
    *reinterpret_cast<uint4*>(dst)      = make_uint4(up[0], up[1], up[2], up[3]);
    *reinterpret_cast<uint4*>(dst + 16) = make_uint4(up[4], up[5], up[6], up[7]);
    *reinterpret_cast<uint2*>(dst + 32) = make_uint2(up[8], up[9]);
}

// ===================== Kernel B: HMMA GRU + output (R14 fp32-accum, proven) ==========
#define GB_WIH  0
#define GB_WHH  30720
#define GB_WFC  61440
#define GB_ANC  61696
#define GB_SMEM 64256

#define W_STR 80

__device__ __forceinline__ void mma16816(float* d, const unsigned* a,
                                         unsigned b0, unsigned b1) {
    asm volatile(
        "mma.sync.aligned.m16n8k16.row.col.f32.f16.f16.f32 "
        "{%0,%1,%2,%3}, {%4,%5,%6,%7}, {%8,%9}, {%0,%1,%2,%3};"
        : "+f"(d[0]), "+f"(d[1]), "+f"(d[2]), "+f"(d[3])
        : "r"(a[0]), "r"(a[1]), "r"(a[2]), "r"(a[3]), "r"(b0), "r"(b1));
}
__device__ __forceinline__ unsigned pack_h2(float lo, float hi) {
    __half2 h = __floats2half2_rn(lo, hi);
    return *reinterpret_cast<unsigned*>(&h);
}
__device__ __forceinline__ int wperm(int n, int k) {
    int kt = k >> 4, r = k & 15;
    int slot = ((r & 7) >> 1) * 4 + (r >> 3) * 2 + (r & 1);
    return n * W_STR + kt * 16 + slot;
}

__global__ __launch_bounds__(128)
void gru_mma_kernel(const float* __restrict__ xyzt,
                    const float* __restrict__ w_ih,
                    const float* __restrict__ w_hh,
                    const float* __restrict__ w_fc,
                    float* __restrict__ out)
{
    extern __shared__ char smc[];
    __half* wih  = reinterpret_cast<__half*>(smc + GB_WIH);
    __half* whh  = reinterpret_cast<__half*>(smc + GB_WHH);
    float*  wfcs = reinterpret_cast<float*>(smc + GB_WFC);
    float*  ancs = reinterpret_cast<float*>(smc + GB_ANC);

    const int tid = threadIdx.x;

    for (int i = tid; i < 192 * 32; i += 128) {
        int n = i >> 5, k = i & 31;
        wih[wperm(n, k)] = __float2half_rn(w_ih[i]);
    }
    for (int i = tid; i < 192 * 64; i += 128) {
        int n = i >> 6, k = i & 63;
        whh[wperm(n, k)] = __float2half_rn(w_hh[i]);
    }
    if (tid < 64) wfcs[tid] = w_fc[tid];
    __syncthreads();

    const int lane  = tid & 31;
    const int wrp   = tid >> 5;
    const int g     = lane >> 2;
    const int t4    = lane & 3;
    const int pbase = wrp * 16;
    const int gpt0  = blockIdx.x * 64 + pbase;
    const int ptA   = gpt0 + g;
    const int ptB   = gpt0 + g + 8;

    float wfr[16];
    #pragma unroll
    for (int jt = 0; jt < 8; ++jt) {
        wfr[2 * jt]     = wfcs[jt * 8 + t4 * 2];
        wfr[2 * jt + 1] = wfcs[jt * 8 + t4 * 2 + 1];
    }

    const __half2 inv2 = __float2half2_rn(INV_SCALE);

    float hD[8][4];
    #pragma unroll
    for (int i = 0; i < 8; ++i)
        { hD[i][0]=0.f; hD[i][1]=0.f; hD[i][2]=0.f; hD[i][3]=0.f; }
    float anc0 = 0.0f, anc1 = 0.0f;

    const __half* eA = g_emb + (size_t)ptA * 384;
    const __half* eB = g_emb + (size_t)ptB * 384;

    for (int p = 0; p < NP; ++p) {
        unsigned ea[2][4];
        #pragma unroll
        for (int kt = 0; kt < 2; ++kt) {
            int l0 = kt * 8 + t4;
            __half2 v0 = __hmul2(*reinterpret_cast<const __half2*>(eA + (l0 * 12 + p) * 2), inv2);
            __half2 v1 = __hmul2(*reinterpret_cast<const __half2*>(eB + (l0 * 12 + p) * 2), inv2);
            __half2 v2 = __hmul2(*reinterpret_cast<const __half2*>(eA + ((l0 + 4) * 12 + p) * 2), inv2);
            __half2 v3 = __hmul2(*reinterpret_cast<const __half2*>(eB + ((l0 + 4) * 12 + p) * 2), inv2);
            ea[kt][0] = *reinterpret_cast<unsigned*>(&v0);
            ea[kt][1] = *reinterpret_cast<unsigned*>(&v1);
            ea[kt][2] = *reinterpret_cast<unsigned*>(&v2);
            ea[kt][3] = *reinterpret_cast<unsigned*>(&v3);
        }
        unsigned ha[4][4];
        if (p > 0) {
            #pragma unroll
            for (int kt = 0; kt < 4; ++kt) {
                ha[kt][0] = pack_h2(hD[2*kt][0],   hD[2*kt][1]);
                ha[kt][1] = pack_h2(hD[2*kt][2],   hD[2*kt][3]);
                ha[kt][2] = pack_h2(hD[2*kt+1][0], hD[2*kt+1][1]);
                ha[kt][3] = pack_h2(hD[2*kt+1][2], hD[2*kt+1][3]);
            }
        }

        float fcp0 = 0.0f, fcp1 = 0.0f;

        #pragma unroll
        for (int jt = 0; jt < 8; ++jt) {
            float aR[4] = {0,0,0,0}, aZ[4] = {0,0,0,0};
            float aN[4] = {0,0,0,0}, aH[4] = {0,0,0,0};
            const int nR = (jt * 8 + g) * W_STR;
            const int nZ = (64 + jt * 8 + g) * W_STR;
            const int nN = (128 + jt * 8 + g) * W_STR;

            #pragma unroll
            for (int kt = 0; kt < 2; ++kt) {
                int ko = kt * 16 + t4 * 4;
                uint2 bR = *reinterpret_cast<const uint2*>(wih + nR + ko);
                uint2 bZ = *reinterpret_cast<const uint2*>(wih + nZ + ko);
                uint2 bN = *reinterpret_cast<const uint2*>(wih + nN + ko);
                mma16816(aR, ea[kt], bR.x, bR.y);
                mma16816(aZ, ea[kt], bZ.x, bZ.y);
                mma16816(aN, ea[kt], bN.x, bN.y);
            }
            if (p > 0) {
                #pragma unroll
                for (int kt = 0; kt < 4; ++kt) {
                    int ko = kt * 16 + t4 * 4;
                    uint2 bR = *reinterpret_cast<const uint2*>(whh + nR + ko);
                    uint2 bZ = *reinterpret_cast<const uint2*>(whh + nZ + ko);
                    uint2 bH = *reinterpret_cast<const uint2*>(whh + nN + ko);
                    mma16816(aR, ha[kt], bR.x, bR.y);
                    mma16816(aZ, ha[kt], bZ.x, bZ.y);
                    mma16816(aH, ha[kt], bH.x, bH.y);
                }
            }
            #pragma unroll
            for (int i = 0; i < 4; ++i) {
                float r = sigm_t(aR[i]);
                float z = sigm_t(aZ[i]);
                float n = tanh_fast(fmaf(r, aH[i], aN[i]));
                float h = fmaf(z, hD[jt][i] - n, n);
                hD[jt][i] = h;
                float wv = wfr[2 * jt + (i & 1)];
                if (i < 2) fcp0 = fmaf(h, wv, fcp0);
                else       fcp1 = fmaf(h, wv, fcp1);
            }
        }
        fcp0 += __shfl_xor_sync(0xffffffffu, fcp0, 1);
        fcp0 += __shfl_xor_sync(0xffffffffu, fcp0, 2);
        fcp1 += __shfl_xor_sync(0xffffffffu, fcp1, 1);
        fcp1 += __shfl_xor_sync(0xffffffffu, fcp1, 2);
        anc0 += __fdiv_rn(fcp0 * 2.0f, 10.0f);
        anc1 += __fdiv_rn(fcp1 * 2.0f, 10.0f);
        if (t4 == 0) {
            ancs[(pbase + g) * NP + p]     = anc0;
            ancs[(pbase + g + 8) * NP + p] = anc1;
        }
    }
    __syncwarp();

    for (int q = 0; q < 16; ++q) {
        int pt = gpt0 + q;
        float t = xyzt[(size_t)pt * 4 + 3];
        float lg[NP];
        float mx = -1e30f;
        #pragma unroll
        for (int p = 0; p < NP; ++p) {
            float a = ancs[(pbase + q) * NP + p];
            float L = -__fdiv_rn(fabsf(t - a), 100.0f);
            lg[p] = L;
            mx = fmaxf(mx, L);
        }
        float s = 0.0f, o = 0.0f;
        #pragma unroll
        for (int p = 0; p < NP; ++p) {
            float w = __expf(lg[p] - mx);
            s += w;
            o += w * __half2float(g_emb[(size_t)pt * 384 + ((lane >> 1) * 12 + p) * 2 + (lane & 1)]);
        }
        out[(size_t)pt * 32 + lane] = __fdiv_rn(o, s) * INV_SCALE;
    }
}

extern "C" void kernel_launch(void* const* d_in, const int* in_sizes, int n_in,
                              void* d_out, int out_size)
{
    const float*  xyzt = (const float*)d_in[0];
    const float2* tab  = (const float2*)d_in[1];
    const float*  w_ih = (const float*)d_in[2];
    const float*  w_hh = (const float*)d_in[3];
    const float*  w_fc = (const float*)d_in[4];
    float* out = (float*)d_out;

    ResParams rp;
    double B = exp((log(4096.0) - log(128.0)) / 15.0);
    for (int l = 0; l < NL; ++l) {
        double v = floor(128.0 * pow(B, (double)l));
        rp.gs[l] = 2.0f / (float)v;
    }

    dim3 gridT((unsigned)(((size_t)NL * TSZ) / 256));
    transpose_kernel<<<gridT, 256>>>(tab);

    dim3 gridA(NPTS / 256, NL);
    gather_kernel<<<gridA, 256>>>(xyzt, rp);

    cudaFuncSetAttribute(gru_mma_kernel, cudaFuncAttributeMaxDynamicSharedMemorySize, GB_SMEM);
    gru_mma_kernel<<<NPTS / 64, 128, GB_SMEM>>>(xyzt, w_ih, w_hh, w_fc, out);
}

// round 17
// speedup vs baseline: 1.5902x; 1.0774x over previous
#include <cuda_runtime.h>
#include <cuda_fp16.h>
#include <stdint.h>
#include <math.h>

#define NPTS 262144
#define NP 10
#define NL 16
#define TSZ (1u << 19)

#define SCALE 8192.0f
#define INV_SCALE (1.0f / 8192.0f)

// emb: per point 16 level-slots of 48B (12 half2: 10 used), 768B/pt
__device__ __half g_emb[(size_t)NPTS * 384];
__device__ uint4  g_tabT[(size_t)NL * TSZ * 4];

struct ResParams { float gs[NL]; };

__device__ __forceinline__ float tanh_fast(float x) {
    float r; asm("tanh.approx.f32 %0, %1;" : "=f"(r) : "f"(x)); return r;
}
__device__ __forceinline__ float sigm_t(float x) {
    return fmaf(0.5f, tanh_fast(0.5f * x), 0.5f);
}

// ===================== Kernel T: table transpose (smem-staged coalesced writes) =====
__global__ __launch_bounds__(256)
void transpose_kernel(const float2* __restrict__ tab)
{
    __shared__ uint4 stg[256 * 5];           // 80B stride per entry: conflict-free
    const int t = threadIdx.x;
    size_t idx = (size_t)blockIdx.x * 256 + t;

    unsigned u[NP];
    #pragma unroll
    for (int p = 0; p < NP; ++p) {
        float2 v = __ldg(tab + (size_t)p * ((size_t)NL * TSZ) + idx);
        __half2 h = __floats2half2_rn(v.x * SCALE, v.y * SCALE);
        u[p] = *reinterpret_cast<unsigned*>(&h);
    }
    stg[t * 5 + 0] = make_uint4(u[0], u[1], u[2], u[3]);
    stg[t * 5 + 1] = make_uint4(u[4], u[5], u[6], u[7]);
    stg[t * 5 + 2] = make_uint4(u[8], u[9], u[8], u[9]);
    stg[t * 5 + 3] = make_uint4(0, 0, 0, 0);
    __syncthreads();

    uint4* dst = g_tabT + ((size_t)blockIdx.x * 256) * 4;
    #pragma unroll
    for (int k = 0; k < 4; ++k) {
        int i = t + k * 256;
        dst[i] = stg[(i >> 2) * 5 + (i & 3)];
    }
}

// ===================== Kernel A: hash-grid gather (unchanged) =====================
__global__ __launch_bounds__(256, 2)
void gather_kernel(const float* __restrict__ xyzt, ResParams rp)
{
    const int l    = blockIdx.y;
    const int ptid = blockIdx.x * 256 + threadIdx.x;

    const float gsv = rp.gs[l];
    float4 ptq = reinterpret_cast<const float4*>(xyzt)[ptid];
    float x = fminf(fmaxf(ptq.x, -1.0f), 1.0f);
    float y = fminf(fmaxf(ptq.y, -1.0f), 1.0f);
    float z = fminf(fmaxf(ptq.z, -1.0f), 1.0f);
    float bx = floorf(__fdiv_rn(x + 1.0f, gsv));
    float by = floorf(__fdiv_rn(y + 1.0f, gsv));
    float bz = floorf(__fdiv_rn(z + 1.0f, gsv));
    float wx = __fdiv_rn(x - (bx * gsv - 1.0f), gsv);
    float wy = __fdiv_rn(y - (by * gsv - 1.0f), gsv);
    float wz = __fdiv_rn(z - (bz * gsv - 1.0f), gsv);

    unsigned ix = (unsigned)(int)bx;
    unsigned iy = (unsigned)(int)by;
    unsigned iz = (unsigned)(int)bz;
    unsigned hy0 = iy * 2654435761u, hy1 = hy0 + 2654435761u;
    unsigned hz0 = iz * 805459861u,  hz1 = hz0 + 805459861u;

    unsigned hidx[8];
    float    wc[8];
    float wx1 = 1.0f - wx, wy1 = 1.0f - wy, wz1 = 1.0f - wz;
    #pragma unroll
    for (int c = 0; c < 8; ++c) {
        unsigned hx = ix + ((c >> 2) & 1);
        unsigned hy = (c & 2) ? hy1 : hy0;
        unsigned hz = (c & 1) ? hz1 : hz0;
        hidx[c] = (hx ^ hy ^ hz) & (TSZ - 1u);
        wc[c] = (((c >> 2) & 1) ? wx : wx1) * ((c & 2) ? wy : wy1) * ((c & 1) ? wz : wz1);
    }

    const uint4* lvl = g_tabT + (size_t)l * TSZ * 4;
    float sx[NP], sy[NP];
    #pragma unroll
    for (int p = 0; p < NP; ++p) { sx[p] = 0.0f; sy[p] = 0.0f; }

    {
        uint4 va[8], vb[8];
        uint2 vcc[8];
        #pragma unroll
        for (int c = 0; c < 8; ++c) {
            const uint4* s = lvl + (size_t)hidx[c] * 4;
            va[c]  = __ldg(s);
            vb[c]  = __ldg(s + 1);
            vcc[c] = __ldg(reinterpret_cast<const uint2*>(s + 2));
        }
        #pragma unroll
        for (int c = 0; c < 8; ++c) {
            float w = wc[c];
            unsigned u[NP] = {va[c].x, va[c].y, va[c].z, va[c].w,
                              vb[c].x, vb[c].y, vb[c].z, vb[c].w,
                              vcc[c].x, vcc[c].y};
            #pragma unroll
            for (int p = 0; p < NP; ++p) {
                float2 f = __half22float2(*reinterpret_cast<__half2*>(&u[p]));
                sx[p] = fmaf(w, f.x, sx[p]);
                sy[p] = fmaf(w, f.y, sy[p]);
            }
        }
    }

    unsigned up[NP];
    #pragma unroll
    for (int p = 0; p < NP; ++p) {
        __half2 h = __floats2half2_rn(sx[p], sy[p]);   // pre-scaled by 8192
        up[p] = *reinterpret_cast<unsigned*>(&h);
    }
    char* dst = reinterpret_cast<char*>(g_emb) + (size_t)ptid * 768 + l * 48;
    *reinterpret_cast<uint4*>(dst)      = make_uint4(up[0], up[1], up[2], up[3]);
    *reinterpret_cast<uint4*>(dst + 16) = make_uint4(up[4], up[5], up[6], up[7]);
    *reinterpret_cast<uint2*>(dst + 32) = make_uint2(up[8], up[9]);
}

// ===================== Kernel B: HMMA GRU + output (256 thr, 128 pts/block) ==========
#define GB_WIH  0
#define GB_WHH  30720
#define GB_WFC  61440
#define GB_ANC  61696
#define GB_SMEM 66816    // +128*10*4 anc

#define W_STR 80

__device__ __forceinline__ void mma16816(float* d, const unsigned* a,
                                         unsigned b0, unsigned b1) {
    asm volatile(
        "mma.sync.aligned.m16n8k16.row.col.f32.f16.f16.f32 "
        "{%0,%1,%2,%3}, {%4,%5,%6,%7}, {%8,%9}, {%0,%1,%2,%3};"
        : "+f"(d[0]), "+f"(d[1]), "+f"(d[2]), "+f"(d[3])
        : "r"(a[0]), "r"(a[1]), "r"(a[2]), "r"(a[3]), "r"(b0), "r"(b1));
}
__device__ __forceinline__ unsigned pack_h2(float lo, float hi) {
    __half2 h = __floats2half2_rn(lo, hi);
    return *reinterpret_cast<unsigned*>(&h);
}
__device__ __forceinline__ int wperm(int n, int k) {
    int kt = k >> 4, r = k & 15;
    int slot = ((r & 7) >> 1) * 4 + (r >> 3) * 2 + (r & 1);
    return n * W_STR + kt * 16 + slot;
}

__global__ __launch_bounds__(256)
void gru_mma_kernel(const float* __restrict__ xyzt,
                    const float* __restrict__ w_ih,
                    const float* __restrict__ w_hh,
                    const float* __restrict__ w_fc,
                    float* __restrict__ out)
{
    extern __shared__ char smc[];
    __half* wih  = reinterpret_cast<__half*>(smc + GB_WIH);
    __half* whh  = reinterpret_cast<__half*>(smc + GB_WHH);
    float*  wfcs = reinterpret_cast<float*>(smc + GB_WFC);
    float*  ancs = reinterpret_cast<float*>(smc + GB_ANC);

    const int tid = threadIdx.x;

    for (int i = tid; i < 192 * 32; i += 256) {
        int n = i >> 5, k = i & 31;
        wih[wperm(n, k)] = __float2half_rn(w_ih[i]);
    }
    for (int i = tid; i < 192 * 64; i += 256) {
        int n = i >> 6, k = i & 63;
        whh[wperm(n, k)] = __float2half_rn(w_hh[i]);
    }
    if (tid < 64) wfcs[tid] = w_fc[tid];
    __syncthreads();

    const int lane  = tid & 31;
    const int wrp   = tid >> 5;             // 0..7
    const int g     = lane >> 2;
    const int t4    = lane & 3;
    const int pbase = wrp * 16;
    const int gpt0  = blockIdx.x * 128 + pbase;
    const int ptA   = gpt0 + g;
    const int ptB   = gpt0 + g + 8;

    float wfr[16];
    #pragma unroll
    for (int jt = 0; jt < 8; ++jt) {
        wfr[2 * jt]     = wfcs[jt * 8 + t4 * 2];
        wfr[2 * jt + 1] = wfcs[jt * 8 + t4 * 2 + 1];
    }

    const __half2 inv2 = __float2half2_rn(INV_SCALE);

    float hD[8][4];
    #pragma unroll
    for (int i = 0; i < 8; ++i)
        { hD[i][0]=0.f; hD[i][1]=0.f; hD[i][2]=0.f; hD[i][3]=0.f; }
    float anc0 = 0.0f, anc1 = 0.0f;

    const __half* eA = g_emb + (size_t)ptA * 384;
    const __half* eB = g_emb + (size_t)ptB * 384;

    for (int p = 0; p < NP; ++p) {
        unsigned ea[2][4];
        #pragma unroll
        for (int kt = 0; kt < 2; ++kt) {
            int l0 = kt * 8 + t4;
            __half2 v0 = __hmul2(*reinterpret_cast<const __half2*>(eA + (l0 * 12 + p) * 2), inv2);
            __half2 v1 = __hmul2(*reinterpret_cast<const __half2*>(eB + (l0 * 12 + p) * 2), inv2);
            __half2 v2 = __hmul2(*reinterpret_cast<const __half2*>(eA + ((l0 + 4) * 12 + p) * 2), inv2);
            __half2 v3 = __hmul2(*reinterpret_cast<const __half2*>(eB + ((l0 + 4) * 12 + p) * 2), inv2);
            ea[kt][0] = *reinterpret_cast<unsigned*>(&v0);
            ea[kt][1] = *reinterpret_cast<unsigned*>(&v1);
            ea[kt][2] = *reinterpret_cast<unsigned*>(&v2);
            ea[kt][3] = *reinterpret_cast<unsigned*>(&v3);
        }
        unsigned ha[4][4];
        if (p > 0) {
            #pragma unroll
            for (int kt = 0; kt < 4; ++kt) {
                ha[kt][0] = pack_h2(hD[2*kt][0],   hD[2*kt][1]);
                ha[kt][1] = pack_h2(hD[2*kt][2],   hD[2*kt][3]);
                ha[kt][2] = pack_h2(hD[2*kt+1][0], hD[2*kt+1][1]);
                ha[kt][3] = pack_h2(hD[2*kt+1][2], hD[2*kt+1][3]);
            }
        }

        float fcp0 = 0.0f, fcp1 = 0.0f;

        #pragma unroll
        for (int jt = 0; jt < 8; ++jt) {
            float aR[4] = {0,0,0,0}, aZ[4] = {0,0,0,0};
            float aN[4] = {0,0,0,0}, aH[4] = {0,0,0,0};
            const int nR = (jt * 8 + g) * W_STR;
            const int nZ = (64 + jt * 8 + g) * W_STR;
            const int nN = (128 + jt * 8 + g) * W_STR;

            #pragma unroll
            for (int kt = 0; kt < 2; ++kt) {
                int ko = kt * 16 + t4 * 4;
                uint2 bR = *reinterpret_cast<const uint2*>(wih + nR + ko);
                uint2 bZ = *reinterpret_cast<const uint2*>(wih + nZ + ko);
                uint2 bN = *reinterpret_cast<const uint2*>(wih + nN + ko);
                mma16816(aR, ea[kt], bR.x, bR.y);
                mma16816(aZ, ea[kt], bZ.x, bZ.y);
                mma16816(aN, ea[kt], bN.x, bN.y);
            }
            if (p > 0) {
                #pragma unroll
                for (int kt = 0; kt < 4; ++kt) {
                    int ko = kt * 16 + t4 * 4;
                    uint2 bR = *reinterpret_cast<const uint2*>(whh + nR + ko);
                    uint2 bZ = *reinterpret_cast<const uint2*>(whh + nZ + ko);
                    uint2 bH = *reinterpret_cast<const uint2*>(whh + nN + ko);
                    mma16816(aR, ha[kt], bR.x, bR.y);
                    mma16816(aZ, ha[kt], bZ.x, bZ.y);
                    mma16816(aH, ha[kt], bH.x, bH.y);
                }
            }
            #pragma unroll
            for (int i = 0; i < 4; ++i) {
                float r = sigm_t(aR[i]);
                float z = sigm_t(aZ[i]);
                float n = tanh_fast(fmaf(r, aH[i], aN[i]));
                float h = fmaf(z, hD[jt][i] - n, n);
                hD[jt][i] = h;
                float wv = wfr[2 * jt + (i & 1)];
                if (i < 2) fcp0 = fmaf(h, wv, fcp0);
                else       fcp1 = fmaf(h, wv, fcp1);
            }
        }
        fcp0 += __shfl_xor_sync(0xffffffffu, fcp0, 1);
        fcp0 += __shfl_xor_sync(0xffffffffu, fcp0, 2);
        fcp1 += __shfl_xor_sync(0xffffffffu, fcp1, 1);
        fcp1 += __shfl_xor_sync(0xffffffffu, fcp1, 2);
        anc0 += __fdiv_rn(fcp0 * 2.0f, 10.0f);
        anc1 += __fdiv_rn(fcp1 * 2.0f, 10.0f);
        if (t4 == 0) {
            ancs[(pbase + g) * NP + p]     = anc0;
            ancs[(pbase + g + 8) * NP + p] = anc1;
        }
    }
    __syncwarp();

    for (int q = 0; q < 16; ++q) {
        int pt = gpt0 + q;
        float t = xyzt[(size_t)pt * 4 + 3];
        float lg[NP];
        float mx = -1e30f;
        #pragma unroll
        for (int p = 0; p < NP; ++p) {
            float a = ancs[(pbase + q) * NP + p];
            float L = -__fdiv_rn(fabsf(t - a), 100.0f);
            lg[p] = L;
            mx = fmaxf(mx, L);
        }
        float s = 0.0f, o = 0.0f;
        #pragma unroll
        for (int p = 0; p < NP; ++p) {
            float w = __expf(lg[p] - mx);
            s += w;
            o += w * __half2float(g_emb[(size_t)pt * 384 + ((lane >> 1) * 12 + p) * 2 + (lane & 1)]);
        }
        out[(size_t)pt * 32 + lane] = __fdiv_rn(o, s) * INV_SCALE;
    }
}

extern "C" void kernel_launch(void* const* d_in, const int* in_sizes, int n_in,
                              void* d_out, int out_size)
{
    const float*  xyzt = (const float*)d_in[0];
    const float2* tab  = (const float2*)d_in[1];
    const float*  w_ih = (const float*)d_in[2];
    const float*  w_hh = (const float*)d_in[3];
    const float*  w_fc = (const float*)d_in[4];
    float* out = (float*)d_out;

    ResParams rp;
    double B = exp((log(4096.0) - log(128.0)) / 15.0);
    for (int l = 0; l < NL; ++l) {
        double v = floor(128.0 * pow(B, (double)l));
        rp.gs[l] = 2.0f / (float)v;
    }

    dim3 gridT((unsigned)(((size_t)NL * TSZ) / 256));
    transpose_kernel<<<gridT, 256>>>(tab);

    dim3 gridA(NPTS / 256, NL);
    gather_kernel<<<gridA, 256>>>(xyzt, rp);

    cudaFuncSetAttribute(gru_mma_kernel, cudaFuncAttributeMaxDynamicSharedMemorySize, GB_SMEM);
    gru_mma_kernel<<<NPTS / 128, 256, GB_SMEM>>>(xyzt, w_ih, w_hh, w_fc, out);
}